// round 4
// baseline (speedup 1.0000x reference)
#include <cuda_runtime.h>
#include <math_constants.h>
#include <cstdint>

// H=W=14, K=6, ST=2, xs={0,2,4,6,8}, M=5, B=32, C=1000
#define BB 32
#define CC 1000
#define HW 196
#define NVAL 145       // 144 rects + total
#define NSTREAM 651    // 625 two-mask + 25 one-mask + 1 total
#define NCHUNK 8
#define CPB 125        // channels per chunk
#define TPB 672

// 12 non-degenerate intervals (prefix space 0..14), same for rows and cols:
//  d=0 (w=6): [2i,2i+6) -> ids 0..4 ; d=1 (w=4): [2m+2,2m+6) -> 5..8 ;
//  d=2 (w=2): [2m+4,2m+6) -> 9..11
__device__ const int d_LO[12] = {0,2,4,6,8,  2,4,6,8,  4,6,8};
__device__ const int d_HI[12] = {6,8,10,12,14,  6,8,10,12,  6,8,10};

__device__ float        g_pval[BB * NCHUNK * NSTREAM];
__device__ int          g_pidx[BB * NCHUNK * NSTREAM];
__device__ unsigned int g_cnt[BB];   // zero-init; self-resetting

__device__ __forceinline__ int cls_id(int a, int b) {
    int d  = a > b ? a - b : b - a;
    int mn = a < b ? a : b;
    if (d == 0) return mn;
    if (d == 1) return 5 + mn;
    if (d == 2) return 9 + mn;
    return -1;  // empty intersection
}

__global__ __launch_bounds__(TPB) void fused_kernel(const float* __restrict__ x,
                                                    float* __restrict__ out) {
    const int chunk = blockIdx.x;
    const int b     = blockIdx.y;
    const int t     = threadIdx.x;

    __shared__ float tile[2][HW];    // double-buffered channel tile
    __shared__ float rseg[14][12];   // per-row sums over 12 col intervals
    __shared__ float rtot[14];
    __shared__ float vals[146];      // 144 rects + total + hard zero
    __shared__ int   spred[NSTREAM];
    __shared__ unsigned char cand[25];
    __shared__ int   do_final;

    // ---- stream -> (offA, offB, offOv); slot 145 = 0, slot 144 = total ----
    int offA = 145, offB = 145, offOv = 145;
    if (t < 625) {
        int q = t % 5, p = (t / 5) % 5, j = (t / 25) % 5, i = t / 125;
        offA = i * 12 + j;                       // winsum(i,j)
        offB = p * 12 + q;                       // winsum(p,q)
        int rip = cls_id(i, p), cjq = cls_id(j, q);
        offOv = (rip < 0 || cjq < 0) ? 145 : (rip * 12 + cjq);
    } else if (t < 650) {
        int ij = t - 625;                        // one-mask stream
        offA = (ij / 5) * 12 + (ij % 5);
    }                                            // t==650: total stream

    const size_t base = ((size_t)b * CC + (size_t)chunk * CPB) * HW;

    // preload channel 0 tile (prefetch group: last 196 threads)
    if (t >= TPB - HW) tile[0][t - (TPB - HW)] = x[base + (t - (TPB - HW))];
    if (t == 0) vals[145] = 0.f;

    float best = -CUDART_INF_F;
    int   bidx = 0;

    for (int k = 0; k < CPB; k++) {
        const int cur = k & 1;
        __syncthreads();  // tile[cur] ready; previous vals reads finished

        if (t < 168) {                           // row segments
            int r = t / 12, ci = t % 12;
            float s = 0.f;
            for (int w = d_LO[ci]; w < d_HI[ci]; w++) s += tile[cur][r * 14 + w];
            rseg[r][ci] = s;
        } else if (t < 182) {                    // row totals
            int r = t - 168;
            float s = 0.f;
            #pragma unroll
            for (int w = 0; w < 14; w++) s += tile[cur][r * 14 + w];
            rtot[r] = s;
        } else if (t >= TPB - HW && k + 1 < CPB) {  // prefetch next tile
            int i = t - (TPB - HW);
            tile[cur ^ 1][i] = x[base + (size_t)(k + 1) * HW + i];
        }
        __syncthreads();  // rseg/rtot ready

        if (t < 144) {                           // rects
            int ri = t / 12, ci = t % 12;
            float s = 0.f;
            for (int r = d_LO[ri]; r < d_HI[ri]; r++) s += rseg[r][ci];
            vals[t] = s;
        } else if (t == 144) {                   // total
            float s = 0.f;
            #pragma unroll
            for (int r = 0; r < 14; r++) s += rtot[r];
            vals[144] = s;
        }
        __syncthreads();  // vals ready

        float v = vals[144] - vals[offA] - vals[offB] + vals[offOv];
        if (v > best) { best = v; bidx = chunk * CPB + k; }  // strict >: first max
    }

    // ---- publish partials ----
    if (t < NSTREAM) {
        int o = (b * NCHUNK + chunk) * NSTREAM + t;
        g_pval[o] = best;
        g_pidx[o] = bidx;
    }
    __threadfence();
    __syncthreads();
    if (t == 0) {
        unsigned int old = atomicAdd(&g_cnt[b], 1u);
        do_final = (old == NCHUNK - 1) ? 1 : 0;
    }
    __syncthreads();
    if (!do_final) return;

    // ---- last block for this batch: reduce + decide ----
    __threadfence();  // make peers' partials visible
    if (t < NSTREAM) {
        float bb = -CUDART_INF_F;
        int bi = 0;
        #pragma unroll
        for (int k = 0; k < NCHUNK; k++) {
            int o = (b * NCHUNK + k) * NSTREAM + t;
            float v = g_pval[o];
            int  id = g_pidx[o];
            if (v > bb) { bb = v; bi = id; }   // ties -> earlier chunk (lower channel)
        }
        spred[t] = bi;
    }
    __syncthreads();

    if (t < 25) {
        int om = spred[625 + t];               // one-mask pred at (i,j)=t
        bool ag = true;
        #pragma unroll
        for (int pq = 0; pq < 25; pq++) ag = ag && (spred[t * 25 + pq] == om);
        cand[t] = (ag && om != spred[650]) ? 1 : 0;
    }
    __syncthreads();

    if (t == 0) {
        int pred = spred[650];
        #pragma unroll
        for (int u = 0; u < 25; u++) {
            if (cand[u]) { pred = spred[625 + u]; break; }  // first True
        }
        out[b] = (float)pred;   // __output__ treated as float32
        g_cnt[b] = 0;           // reset for next invocation / graph replay
    }
}

extern "C" void kernel_launch(void* const* d_in, const int* in_sizes, int n_in,
                              void* d_out, int out_size) {
    const float* x = (const float*)d_in[0];
    float* out = (float*)d_out;
    dim3 grid(NCHUNK, BB);
    fused_kernel<<<grid, TPB>>>(x, out);
}

// round 5
// speedup vs baseline: 2.1003x; 2.1003x over previous
#include <cuda_runtime.h>
#include <math_constants.h>
#include <cstdint>

// H=W=14, K=6, ST=2, xs={0,2,4,6,8}, M=5, B=32, C=1000
#define BB 32
#define CC 1000
#define HW 196
#define NVAL 145       // 144 rects + total
#define NSTREAM 651    // 625 two-mask + 25 one-mask + 1 total
#define NCHUNK 8
#define CPB 125        // channels per chunk (k2)
#define T2 672
#define GRP 25         // channels staged per k2 round
#define K1_WPB 8       // warps per block in k1
#define K1_SMW 572     // smem floats per warp: 196 tile + 112 pp + 168 rs + 96 qq

// Scratch
__device__ float g_rect[BB * CC * NVAL];          // ~18.6 MB
__device__ float g_pval[BB * NCHUNK * NSTREAM];
__device__ int   g_pidx[BB * NCHUNK * NSTREAM];

// interval class id for two intervals [2a,2a+6) vs [2b,2b+6) intersection:
//  d=0 -> ids 0..4 (w=6), d=1 -> 5..8 (w=4), d=2 -> 9..11 (w=2), else empty
__device__ __forceinline__ int cls_id(int a, int b) {
    int d  = a > b ? a - b : b - a;
    int mn = a < b ? a : b;
    if (d == 0) return mn;
    if (d == 1) return 5 + mn;
    if (d == 2) return 9 + mn;
    return -1;
}

// interval id -> pair-unit bounds [lo2, hi2) (all window bounds are even)
__device__ __forceinline__ void seg2(int ci, int& lo2, int& hi2) {
    if (ci < 5)      { lo2 = ci;     hi2 = ci + 3; }   // width 6
    else if (ci < 9) { lo2 = ci - 4; hi2 = ci - 2; }   // width 4
    else             { lo2 = ci - 7; hi2 = ci - 6; }   // width 2
}

// ---------------------------------------------------------------------------
// K1: warp-per-channel rect builder. No block barriers.
// Layout per warp in smem: tile[196] | pp[14][8] | rs[14][12] | qq[8][12]
// ---------------------------------------------------------------------------
__global__ __launch_bounds__(32 * K1_WPB) void k1_rects(const float* __restrict__ x) {
    const int lane = threadIdx.x & 31;
    const int w    = threadIdx.x >> 5;
    const int bc   = blockIdx.x * K1_WPB + w;   // b*1000 + c

    extern __shared__ float sm_raw[];
    float* T  = sm_raw + w * K1_SMW;
    float* PP = T + 196;     // row pair-prefix: PP[r*8 + m], PP[r*8]=0
    float* RS = PP + 112;    // row segments: RS[r*12 + ci]
    float* QQ = RS + 168;    // col pair-prefix over rows: QQ[m*12 + ci], QQ[0..11]=0

    // load tile (49 float4)
    const float4* xp4 = (const float4*)(x + (size_t)bc * HW);
    float4* T4 = (float4*)T;
    for (int i = lane; i < 49; i += 32) T4[i] = xp4[i];
    __syncwarp();

    // per-row pair prefix (lanes 0..13)
    if (lane < 14) {
        const float* row = T + lane * 14;
        float s = 0.f;
        PP[lane * 8] = 0.f;
        #pragma unroll
        for (int m = 0; m < 7; m++) {
            s += row[2 * m] + row[2 * m + 1];
            PP[lane * 8 + m + 1] = s;
        }
    }
    __syncwarp();

    // row segments (168)
    for (int e = lane; e < 168; e += 32) {
        int r = e / 12, ci = e % 12;
        int lo2, hi2; seg2(ci, lo2, hi2);
        RS[e] = PP[r * 8 + hi2] - PP[r * 8 + lo2];
    }
    __syncwarp();

    float* go = g_rect + (size_t)bc * NVAL;

    // column pair prefix (lanes 0..11); lane 12 computes total
    if (lane < 12) {
        float s = 0.f;
        QQ[lane] = 0.f;
        #pragma unroll
        for (int m = 0; m < 7; m++) {
            s += RS[(2 * m) * 12 + lane] + RS[(2 * m + 1) * 12 + lane];
            QQ[(m + 1) * 12 + lane] = s;
        }
    } else if (lane == 12) {
        float s = 0.f;
        #pragma unroll
        for (int r = 0; r < 14; r++) s += PP[r * 8 + 7];
        go[144] = s;                                  // total
    }
    __syncwarp();

    // rects (144)
    for (int e = lane; e < 144; e += 32) {
        int ri = e / 12, ci = e % 12;
        int lo2, hi2; seg2(ri, lo2, hi2);
        go[e] = QQ[hi2 * 12 + ci] - QQ[lo2 * 12 + ci];
    }
}

// ---------------------------------------------------------------------------
// K2: per (chunk,b) partial argmax over 125 channels for 651 streams.
// Stage GRP=25 channels/round -> 10 barriers total.
// score = vals[144] - vals[offA] - vals[offB] + vals[offOv]; slot 145 == 0.
// ---------------------------------------------------------------------------
__global__ __launch_bounds__(T2) void k2_argmax() {
    const int chunk = blockIdx.x;
    const int b     = blockIdx.y;
    const int t     = threadIdx.x;

    __shared__ float s[GRP][146];

    int offA = 145, offB = 145, offOv = 145;
    if (t < 625) {
        int q = t % 5, p = (t / 5) % 5, j = (t / 25) % 5, i = t / 125;
        offA = i * 12 + j;
        offB = p * 12 + q;
        int rip = cls_id(i, p), cjq = cls_id(j, q);
        offOv = (rip < 0 || cjq < 0) ? 145 : (rip * 12 + cjq);
    } else if (t < 650) {
        int ij = t - 625;
        offA = (ij / 5) * 12 + (ij % 5);
    }                                   // t==650: total stream

    if (t < GRP) s[t][145] = 0.f;       // persistent zero slot (never overwritten)

    const int c0 = chunk * CPB;
    const float* gr = g_rect + ((size_t)b * CC + c0) * NVAL;

    float best = -CUDART_INF_F;
    int   bidx = 0;

    for (int r0 = 0; r0 < CPB; r0 += GRP) {
        __syncthreads();   // previous round's reads complete (also covers zero-init)
        for (int idx = t; idx < GRP * NVAL; idx += T2) {
            int g = idx / NVAL, e = idx % NVAL;
            s[g][e] = gr[(size_t)(r0 + g) * NVAL + e];
        }
        __syncthreads();
        #pragma unroll
        for (int g = 0; g < GRP; g++) {
            float v = s[g][144] - s[g][offA] - s[g][offB] + s[g][offOv];
            if (v > best) { best = v; bidx = c0 + r0 + g; }   // strict >: first max
        }
    }

    if (t < NSTREAM) {
        int o = (b * NCHUNK + chunk) * NSTREAM + t;
        g_pval[o] = best;
        g_pidx[o] = bidx;
    }
}

// ---------------------------------------------------------------------------
// K3: reduce chunk partials; decision logic; float output.
// ---------------------------------------------------------------------------
__global__ __launch_bounds__(T2) void k3_decide(float* __restrict__ out) {
    const int b = blockIdx.x;
    const int t = threadIdx.x;

    __shared__ int spred[NSTREAM];
    __shared__ unsigned char cand[25];

    if (t < NSTREAM) {
        float bb = -CUDART_INF_F;
        int bi = 0;
        #pragma unroll
        for (int k = 0; k < NCHUNK; k++) {
            int o = (b * NCHUNK + k) * NSTREAM + t;
            float v = g_pval[o];
            int  id = g_pidx[o];
            if (v > bb) { bb = v; bi = id; }  // ties -> earlier chunk (lower channel)
        }
        spred[t] = bi;
    }
    __syncthreads();

    if (t < 25) {
        int om = spred[625 + t];
        bool ag = true;
        #pragma unroll
        for (int pq = 0; pq < 25; pq++) ag = ag && (spred[t * 25 + pq] == om);
        cand[t] = (ag && om != spred[650]) ? 1 : 0;
    }
    __syncthreads();

    if (t == 0) {
        int pred = spred[650];
        #pragma unroll
        for (int u = 0; u < 25; u++) {
            if (cand[u]) { pred = spred[625 + u]; break; }   // first True
        }
        out[b] = (float)pred;
    }
}

// ---------------------------------------------------------------------------
extern "C" void kernel_launch(void* const* d_in, const int* in_sizes, int n_in,
                              void* d_out, int out_size) {
    const float* x = (const float*)d_in[0];
    float* out = (float*)d_out;

    const int smem1 = K1_WPB * K1_SMW * sizeof(float);
    k1_rects<<<BB * CC / K1_WPB, 32 * K1_WPB, smem1>>>(x);
    dim3 g2(NCHUNK, BB);
    k2_argmax<<<g2, T2>>>();
    k3_decide<<<BB, T2>>>(out);
}

// round 6
// speedup vs baseline: 3.1174x; 1.4843x over previous
#include <cuda_runtime.h>
#include <math_constants.h>
#include <cstdint>

// H=W=14, K=6, ST=2, xs={0,2,4,6,8}, M=5, B=32, C=1000
#define BB 32
#define CC 1000
#define HW 196
#define NVAL 145       // 144 rects + total
#define NPAIR 325      // unordered (u,v), u<=v, u,v in 0..24
#define NSTREAM 351    // 325 pair + 25 one-mask + 1 total
#define NCHUNK 8
#define CPB 125
#define T2 384
#define GRP 25
#define K1_WPB 8

__device__ float g_rect[BB * CC * NVAL];          // ~18.6 MB
__device__ float g_pval[BB * NCHUNK * NSTREAM];
__device__ int   g_pidx[BB * NCHUNK * NSTREAM];

// interval class id for [2a,2a+6) ∩ [2b,2b+6): d=0 -> 0..4 (w6),
// d=1 -> 5..8 (w4), d=2 -> 9..11 (w2), else empty
__device__ __forceinline__ int cls_id(int a, int b) {
    int d  = a > b ? a - b : b - a;
    int mn = a < b ? a : b;
    if (d == 0) return mn;
    if (d == 1) return 5 + mn;
    if (d == 2) return 9 + mn;
    return -1;
}

// interval id -> pair-unit bounds [lo2, hi2)
__device__ __forceinline__ void seg2(int ci, int& lo2, int& hi2) {
    if (ci < 5)      { lo2 = ci;     hi2 = ci + 3; }   // width 6
    else if (ci < 9) { lo2 = ci - 4; hi2 = ci - 2; }   // width 4
    else             { lo2 = ci - 7; hi2 = ci - 6; }   // width 2
}

// ---------------------------------------------------------------------------
// K1: warp-per-channel. Registers + shuffles; tiny 8x8 S2 table in smem.
// S2[rr][m] = sum over rows r<2rr of RP[r][m], RP = row col-pair prefix.
// rect[ri][ci] = S2[hi2r][hi2c]-S2[lo2r][hi2c]-S2[hi2r][lo2c]+S2[lo2r][lo2c]
// ---------------------------------------------------------------------------
__global__ __launch_bounds__(32 * K1_WPB) void k1_rects(const float* __restrict__ x) {
    const int lane = threadIdx.x & 31;
    const int w    = threadIdx.x >> 5;
    const int bc   = blockIdx.x * K1_WPB + w;

    __shared__ float s2all[K1_WPB][65];
    float* S2 = &s2all[w][0];            // S2[rr*8 + m]

    const int h = lane >> 4;             // 0: cols 0-7 ; 1: cols 8-13
    const int r = lane & 15;             // row 0..13 (r=14,15 idle)
    const bool act = (r < 14);

    const float* xp = x + (size_t)bc * HW + r * 14;

    // Phase A: per-row pair prefix in registers.
    // h0: rp1..rp4 = RP[r][1..4] ; h1: rp1..rp3 = RP[r][5..7] (after +c4)
    float rp1 = 0.f, rp2 = 0.f, rp3 = 0.f, rp4 = 0.f;
    if (act) {
        if (h == 0) {
            float2 a = *(const float2*)(xp + 0);
            float2 b = *(const float2*)(xp + 2);
            float2 c = *(const float2*)(xp + 4);
            float2 d = *(const float2*)(xp + 6);
            rp1 = a.x + a.y;
            rp2 = rp1 + (b.x + b.y);
            rp3 = rp2 + (c.x + c.y);
            rp4 = rp3 + (d.x + d.y);
        } else {
            float2 a = *(const float2*)(xp + 8);
            float2 b = *(const float2*)(xp + 10);
            float2 c = *(const float2*)(xp + 12);
            rp1 = a.x + a.y;
            rp2 = rp1 + (b.x + b.y);
            rp3 = rp2 + (c.x + c.y);
        }
    }
    // broadcast c4 (= RP[r][4], held in h0 lane r) to h1 lane 16+r
    float c4 = __shfl_sync(0xFFFFFFFFu, rp4, r);
    if (h == 1 && act) { rp1 += c4; rp2 += c4; rp3 += c4; }

    // Phase B: pair adjacent rows, then inclusive Kogge-Stone scan over k=r/2.
    float q1 = rp1 + __shfl_xor_sync(0xFFFFFFFFu, rp1, 1);
    float q2 = rp2 + __shfl_xor_sync(0xFFFFFFFFu, rp2, 1);
    float q3 = rp3 + __shfl_xor_sync(0xFFFFFFFFu, rp3, 1);
    float q4 = rp4 + __shfl_xor_sync(0xFFFFFFFFu, rp4, 1);
    const int k = r >> 1;                 // 0..6 valid
    #pragma unroll
    for (int s = 1; s < 8; s <<= 1) {
        float t1 = __shfl_up_sync(0xFFFFFFFFu, q1, 2 * s);
        float t2 = __shfl_up_sync(0xFFFFFFFFu, q2, 2 * s);
        float t3 = __shfl_up_sync(0xFFFFFFFFu, q3, 2 * s);
        float t4 = __shfl_up_sync(0xFFFFFFFFu, q4, 2 * s);
        if (k >= s) { q1 += t1; q2 += t2; q3 += t3; q4 += t4; }
    }

    float* go = g_rect + (size_t)bc * NVAL;

    // store S2 (even valid lanes hold inclusive T[k] = S2[k+1])
    if (act && (r & 1) == 0) {
        int row = (k + 1) * 8;
        if (h == 0) {
            S2[row + 1] = q1; S2[row + 2] = q2; S2[row + 3] = q3; S2[row + 4] = q4;
        } else {
            S2[row + 5] = q1; S2[row + 6] = q2; S2[row + 7] = q3;
        }
    }
    if (lane < 8)                S2[lane] = 0.f;            // rr = 0 row
    if (lane >= 8 && lane < 15)  S2[(lane - 7) * 8] = 0.f;  // m = 0 column
    if (lane == 28) go[144] = q3;                           // total = S2[7][7]
    __syncwarp();

    // Phase C: 144 rects, lanes 0..23 (ci = lane%12, row parity = lane/12)
    if (lane < 24) {
        int ci = lane, rbase = 0;
        if (lane >= 12) { ci = lane - 12; rbase = 1; }
        int lo2c, hi2c; seg2(ci, lo2c, hi2c);
        #pragma unroll
        for (int kk = 0; kk < 6; kk++) {
            int ri = rbase + 2 * kk;
            int lo2r, hi2r; seg2(ri, lo2r, hi2r);
            float v = S2[hi2r * 8 + hi2c] - S2[lo2r * 8 + hi2c]
                    - S2[hi2r * 8 + lo2c] + S2[lo2r * 8 + lo2c];
            go[ri * 12 + ci] = v;
        }
    }
}

// ---------------------------------------------------------------------------
// K2: per (chunk,b) partial argmax over 125 channels for 351 streams
// (symmetry: two[ij,pq] == two[pq,ij]).
// ---------------------------------------------------------------------------
__global__ __launch_bounds__(T2) void k2_argmax() {
    const int chunk = blockIdx.x;
    const int b     = blockIdx.y;
    const int t     = threadIdx.x;

    __shared__ float s[GRP][146];

    int offA = 145, offB = 145, offOv = 145;
    if (t < NPAIR) {
        int u = 0, t0 = t;
        while (t0 >= 25 - u) { t0 -= 25 - u; u++; }
        int v = u + t0;
        int i = u / 5, j = u % 5, p = v / 5, q = v % 5;
        offA = i * 12 + j;
        offB = p * 12 + q;
        int rip = cls_id(i, p), cjq = cls_id(j, q);
        offOv = (rip < 0 || cjq < 0) ? 145 : (rip * 12 + cjq);
    } else if (t < NPAIR + 25) {
        int ij = t - NPAIR;
        offA = (ij / 5) * 12 + (ij % 5);
    }                                   // t == 350: total stream

    if (t < GRP) s[t][145] = 0.f;       // persistent zero slot

    const int c0 = chunk * CPB;
    const float* gr = g_rect + ((size_t)b * CC + c0) * NVAL;

    float best = -CUDART_INF_F;
    int   bidx = 0;

    for (int r0 = 0; r0 < CPB; r0 += GRP) {
        __syncthreads();
        for (int idx = t; idx < GRP * NVAL; idx += T2) {
            int g = idx / NVAL, e = idx % NVAL;
            s[g][e] = gr[(size_t)(r0 + g) * NVAL + e];
        }
        __syncthreads();
        #pragma unroll
        for (int g = 0; g < GRP; g++) {
            float v = s[g][144] - s[g][offA] - s[g][offB] + s[g][offOv];
            if (v > best) { best = v; bidx = c0 + r0 + g; }   // strict >: first max
        }
    }

    if (t < NSTREAM) {
        int o = (b * NCHUNK + chunk) * NSTREAM + t;
        g_pval[o] = best;
        g_pidx[o] = bidx;
    }
}

// ---------------------------------------------------------------------------
// K3: reduce chunk partials; expand symmetric pairs; decide; float output.
// ---------------------------------------------------------------------------
__global__ __launch_bounds__(T2) void k3_decide(float* __restrict__ out) {
    const int b = blockIdx.x;
    const int t = threadIdx.x;

    __shared__ int spred[NSTREAM];
    __shared__ unsigned char cand[25];

    if (t < NSTREAM) {
        float bb = -CUDART_INF_F;
        int bi = 0;
        #pragma unroll
        for (int kc = 0; kc < NCHUNK; kc++) {
            int o = (b * NCHUNK + kc) * NSTREAM + t;
            float v = g_pval[o];
            int  id = g_pidx[o];
            if (v > bb) { bb = v; bi = id; }  // ties -> earlier chunk
        }
        spred[t] = bi;
    }
    __syncthreads();

    if (t < 25) {
        int om = spred[NPAIR + t];
        bool ag = true;
        #pragma unroll
        for (int pq = 0; pq < 25; pq++) {
            int a  = t < pq ? t : pq;
            int bb2 = t < pq ? pq : t;
            int idx = a * 25 - (a * (a - 1)) / 2 + (bb2 - a);
            ag = ag && (spred[idx] == om);
        }
        cand[t] = (ag && om != spred[350]) ? 1 : 0;
    }
    __syncthreads();

    if (t == 0) {
        int pred = spred[350];
        #pragma unroll
        for (int u = 0; u < 25; u++) {
            if (cand[u]) { pred = spred[NPAIR + u]; break; }   // first True
        }
        out[b] = (float)pred;   // __output__ is float32
    }
}

// ---------------------------------------------------------------------------
extern "C" void kernel_launch(void* const* d_in, const int* in_sizes, int n_in,
                              void* d_out, int out_size) {
    const float* x = (const float*)d_in[0];
    float* out = (float*)d_out;

    k1_rects<<<BB * CC / K1_WPB, 32 * K1_WPB>>>(x);
    dim3 g2(NCHUNK, BB);
    k2_argmax<<<g2, T2>>>();
    k3_decide<<<BB, T2>>>(out);
}